// round 6
// baseline (speedup 1.0000x reference)
#include <cuda_runtime.h>

#define BN 256
#define CN 1024
#define HW 169        // 13*13
#define SPLIT 4       // -> 1024 accum blocks
#define Z_CONST 17.079468445347132f   // 2*pi*e
#define EPS_CONST 1e-6f

// Per-(b, split, moment, channel) partials: S, Sx, Sy, Sr=Σ(wx^2+wy^2)f.
// 256*4*4*1024 floats = 16.8 MB (fits L2 -> final kernel reads are L2 hits).
__device__ float g_part[BN * SPLIT * 4 * CN];

// packed fp32x2 ops (ptxas won't auto-fuse; PTX-only)
#define PACK2(d, lo, hi)   asm("mov.b64 %0, {%1, %2};" : "=l"(d) : "f"(lo), "f"(hi))
#define UNPACK2(lo, hi, a) asm("mov.b64 {%0, %1}, %2;" : "=f"(lo), "=f"(hi) : "l"(a))
#define ADD2(d, a, b)      asm("add.rn.f32x2 %0, %1, %2;" : "=l"(d) : "l"(a), "l"(b))
#define FMA2(d, a, b, c)   asm("fma.rn.f32x2 %0, %1, %2, %3;" : "=l"(d) : "l"(a), "l"(b), "l"(c))

// ---------------------------------------------------------------------------
// Kernel 1: 128 threads/block, thread owns channels {4t..4t+3, 512+4t..512+4t+3}.
// 3-stage pipeline per position: prefetch k+1 / exp+warp-partial k / FMA k-1.
// One nw=4 barrier per position; denominators via double-buffered smem.
// ---------------------------------------------------------------------------
__global__ __launch_bounds__(128, 5) void accum_kernel(const float* __restrict__ x,
                                                       float* __restrict__ out) {
    if (blockIdx.x == 0 && threadIdx.x == 0) out[0] = 0.0f;

    const int b    = blockIdx.x >> 2;
    const int sp   = blockIdx.x & 3;
    const int p0   = (sp * HW) >> 2;           // 0,42,84,126
    const int p1   = ((sp + 1) * HW) >> 2;     // 42,84,126,169
    const int n    = p1 - p0;
    const int tid  = threadIdx.x;
    const int wid  = tid >> 5;
    const int lane = tid & 31;

    __shared__ __align__(16) float red[2][4];  // [buf][warp]

    const float4* __restrict__ xb = (const float4*)(x + (size_t)b * HW * CN);

    unsigned long long S[4]  = {0,0,0,0};
    unsigned long long Sx[4] = {0,0,0,0};
    unsigned long long Sy[4] = {0,0,0,0};
    unsigned long long Sr[4] = {0,0,0,0};

    // incremental spatial weights for the delayed (F-stage) position
    const int h0 = p0 / 13;
    float wx = (float)(h0 + 1);
    float wy = (float)(p0 - h0 * 13 + 1);

    // prologue: load position p0 (channels 4t.. and 512+4t..)
    float4 curA = __ldcs(xb + (size_t)p0 * 256 + tid);
    float4 curB = __ldcs(xb + (size_t)p0 * 256 + tid + 128);

    unsigned long long pe[4] = {0,0,0,0};      // prev-position packed exps

    for (int k = 0; k < n; ++k) {
        // ---- Stage E: exps of position k (consume cur before prefetch) ----
        float e0 = __expf(curA.x), e1 = __expf(curA.y);
        float e2 = __expf(curA.z), e3 = __expf(curA.w);
        float e4 = __expf(curB.x), e5 = __expf(curB.y);
        float e6 = __expf(curB.z), e7 = __expf(curB.w);
        unsigned long long e[4];
        PACK2(e[0], e0, e1); PACK2(e[1], e2, e3);
        PACK2(e[2], e4, e5); PACK2(e[3], e6, e7);

        // ---- Stage L: prefetch position k+1 ----
        if (k + 1 < n) {
            curA = __ldcs(xb + (size_t)(p0 + k + 1) * 256 + tid);
            curB = __ldcs(xb + (size_t)(p0 + k + 1) * 256 + tid + 128);
        }

        // ---- warp partial of position k ----
        unsigned long long t0, t1;
        ADD2(t0, e[0], e[1]); ADD2(t1, e[2], e[3]);
        ADD2(t0, t0, t1);
        float lo, hi; UNPACK2(lo, hi, t0);
        float s = lo + hi;
#pragma unroll
        for (int m = 16; m > 0; m >>= 1)
            s += __shfl_xor_sync(0xffffffffu, s, m);
        if (lane == 0) red[k & 1][wid] = s;

        // ---- Stage F: accumulate position k-1 (denom published last barrier) ----
        if (k >= 1) {
            float4 r = *(const float4*)red[(k - 1) & 1];
            float den = (r.x + r.y) + (r.z + r.w);
            float inv = __fdividef(1.0f, den);
            float w1  = inv * wx;
            float w2  = inv * wy;
            float wr  = fmaf(wx, wx, wy * wy) * inv;
            unsigned long long inv2, w12, w22, wr2;
            PACK2(inv2, inv, inv); PACK2(w12, w1, w1);
            PACK2(w22, w2, w2);    PACK2(wr2, wr, wr);
#pragma unroll
            for (int i = 0; i < 4; ++i) {
                FMA2(S[i],  inv2, pe[i], S[i]);
                FMA2(Sx[i], w12,  pe[i], Sx[i]);
                FMA2(Sy[i], w22,  pe[i], Sy[i]);
                FMA2(Sr[i], wr2,  pe[i], Sr[i]);
            }
            wy += 1.0f;
            if (wy > 13.0f) { wy = 1.0f; wx += 1.0f; }
        }

        __syncthreads();

#pragma unroll
        for (int i = 0; i < 4; ++i) pe[i] = e[i];
    }

    // ---- epilogue: accumulate final position n-1 ----
    {
        float4 r = *(const float4*)red[(n - 1) & 1];
        float den = (r.x + r.y) + (r.z + r.w);
        float inv = __fdividef(1.0f, den);
        float w1  = inv * wx;
        float w2  = inv * wy;
        float wr  = fmaf(wx, wx, wy * wy) * inv;
        unsigned long long inv2, w12, w22, wr2;
        PACK2(inv2, inv, inv); PACK2(w12, w1, w1);
        PACK2(w22, w2, w2);    PACK2(wr2, wr, wr);
#pragma unroll
        for (int i = 0; i < 4; ++i) {
            FMA2(S[i],  inv2, pe[i], S[i]);
            FMA2(Sx[i], w12,  pe[i], Sx[i]);
            FMA2(Sy[i], w22,  pe[i], Sy[i]);
            FMA2(Sr[i], wr2,  pe[i], Sr[i]);
        }
    }

    // ---- coalesced partial stores: [B][SPLIT][4][CN] ----
    float* gp = g_part + (size_t)(b * SPLIT + sp) * 4 * CN;
    const int o1 = tid * 4;          // channels 4t..
    const int o2 = 512 + tid * 4;    // channels 512+4t..
    *(ulonglong2*)(gp + 0 * CN + o1) = make_ulonglong2(S[0],  S[1]);
    *(ulonglong2*)(gp + 0 * CN + o2) = make_ulonglong2(S[2],  S[3]);
    *(ulonglong2*)(gp + 1 * CN + o1) = make_ulonglong2(Sx[0], Sx[1]);
    *(ulonglong2*)(gp + 1 * CN + o2) = make_ulonglong2(Sx[2], Sx[3]);
    *(ulonglong2*)(gp + 2 * CN + o1) = make_ulonglong2(Sy[0], Sy[1]);
    *(ulonglong2*)(gp + 2 * CN + o2) = make_ulonglong2(Sy[2], Sy[3]);
    *(ulonglong2*)(gp + 3 * CN + o1) = make_ulonglong2(Sr[0], Sr[1]);
    *(ulonglong2*)(gp + 3 * CN + o2) = make_ulonglong2(Sr[2], Sr[3]);
}

// ---------------------------------------------------------------------------
// Kernel 2: sum splits, per-(b,c) det, block reduce, atomicAdd scalar.
// 256 blocks x 256 thr; thread owns 4 channels (float4 loads, mostly L2 hits).
// ---------------------------------------------------------------------------
__global__ __launch_bounds__(256) void final_kernel(float* __restrict__ out) {
    const int b   = blockIdx.x;
    const int tid = threadIdx.x;
    const int c4  = tid << 2;

    float m0[4] = {0,0,0,0}, m1[4] = {0,0,0,0}, m2[4] = {0,0,0,0}, m3[4] = {0,0,0,0};
#pragma unroll
    for (int s = 0; s < SPLIT; ++s) {
        const float* gs = g_part + (size_t)(b * SPLIT + s) * 4 * CN;
        float4 a0 = *(const float4*)(gs + 0 * CN + c4);
        float4 a1 = *(const float4*)(gs + 1 * CN + c4);
        float4 a2 = *(const float4*)(gs + 2 * CN + c4);
        float4 a3 = *(const float4*)(gs + 3 * CN + c4);
        m0[0] += a0.x; m0[1] += a0.y; m0[2] += a0.z; m0[3] += a0.w;
        m1[0] += a1.x; m1[1] += a1.y; m1[2] += a1.z; m1[3] += a1.w;
        m2[0] += a2.x; m2[1] += a2.y; m2[2] += a2.z; m2[3] += a2.w;
        m3[0] += a3.x; m3[1] += a3.y; m3[2] += a3.z; m3[3] += a3.w;
    }

    float acc = 0.0f;
#pragma unroll
    for (int j = 0; j < 4; ++j) {
        float s     = m0[j] + EPS_CONST;
        float inv_s = 1.0f / s;
        float mx    = m1[j] * inv_s;
        float my    = m2[j] * inv_s;
        float num   = m3[j] - 2.0f * (mx * m1[j] + my * m2[j])
                    + (mx * mx + my * my) * m0[j];
        float d     = num * inv_s * (1.0f / 169.0f);
        acc = fmaf(d * d, Z_CONST, acc);
    }

#pragma unroll
    for (int msk = 16; msk > 0; msk >>= 1)
        acc += __shfl_xor_sync(0xffffffffu, acc, msk);

    __shared__ float wsum[8];
    if ((tid & 31) == 0) wsum[tid >> 5] = acc;
    __syncthreads();
    if (tid == 0) {
        float t = ((wsum[0] + wsum[1]) + (wsum[2] + wsum[3]))
                + ((wsum[4] + wsum[5]) + (wsum[6] + wsum[7]));
        atomicAdd(out, t * (1.0f / (float)(BN * CN)));
    }
}

// ---------------------------------------------------------------------------
extern "C" void kernel_launch(void* const* d_in, const int* in_sizes, int n_in,
                              void* d_out, int out_size) {
    const float* x = (const float*)d_in[0];
    float* out = (float*)d_out;

    accum_kernel<<<BN * SPLIT, 128>>>(x, out);
    final_kernel<<<BN, 256>>>(out);
}

// round 7
// speedup vs baseline: 1.1069x; 1.1069x over previous
#include <cuda_runtime.h>

#define BN 256
#define CN 1024
#define HW 169        // 13*13
#define SPLIT 2       // -> 512 accum blocks = single wave
#define Z_CONST 17.079468445347132f   // 2*pi*e
#define EPS_CONST 1e-6f

// Per-(b, split, moment, channel) partials: S, Sx, Sy, Sr=Σ(wx^2+wy^2)f.
// 256*2*4*1024 floats = 8.4 MB -> fully L2 resident.
__device__ float g_part[BN * SPLIT * 4 * CN];

// packed fp32x2 ops (PTX-only; ptxas won't auto-fuse)
#define PACK2(d, lo, hi)   asm("mov.b64 %0, {%1, %2};" : "=l"(d) : "f"(lo), "f"(hi))
#define ADD2(d, a, b)      asm("add.rn.f32x2 %0, %1, %2;" : "=l"(d) : "l"(a), "l"(b))
#define FMA2(d, a, b, c)   asm("fma.rn.f32x2 %0, %1, %2, %3;" : "=l"(d) : "l"(a), "l"(b), "l"(c))

// ---------------------------------------------------------------------------
// Kernel 1: 256 thr/block, thread owns channels [4t,4t+4).
// True distance-2 prefetch via buf[k&1] ring (unroll 2 -> static indices;
// exps consume the registers, then the k+2 LDG overwrites them: WAR, no wait).
// Pipeline: E(exp k) / L(load k+2) / warp+smem partial k / F(accumulate k-1).
// ---------------------------------------------------------------------------
__global__ __launch_bounds__(256, 5) void accum_kernel(const float* __restrict__ x,
                                                       float* __restrict__ out) {
    if (blockIdx.x == 0 && threadIdx.x == 0) out[0] = 0.0f;

    const int b    = blockIdx.x >> 1;
    const int sp   = blockIdx.x & 1;
    const int p0   = sp ? 85 : 0;
    const int p1   = sp ? HW : 85;
    const int n    = p1 - p0;
    const int tid  = threadIdx.x;
    const int wid  = tid >> 5;
    const int lane = tid & 31;

    __shared__ __align__(16) float red[2][8];  // [buf][warp]

    const float4* __restrict__ xb = (const float4*)(x + (size_t)b * HW * CN) + tid;

    unsigned long long S[2]  = {0, 0};
    unsigned long long Sx[2] = {0, 0};
    unsigned long long Sy[2] = {0, 0};
    unsigned long long Sr[2] = {0, 0};

    // incremental spatial weights for the (delayed) F-stage position
    const int h0 = p0 / 13;
    float wx = (float)(h0 + 1);
    float wy = (float)(p0 - h0 * 13 + 1);

    // prologue: two positions in flight
    float4 buf[2];
    buf[0] = __ldcs(xb + (size_t)p0 * 256);
    buf[1] = (n > 1) ? __ldcs(xb + (size_t)(p0 + 1) * 256) : buf[0];

    unsigned long long pe0 = 0, pe1 = 0;   // prev-position packed exps

#pragma unroll 2
    for (int k = 0; k < n; ++k) {
        // ---- Stage E: exps of position k (reads buf[k&1] registers) ----
        float e0 = __expf(buf[k & 1].x), e1 = __expf(buf[k & 1].y);
        float e2 = __expf(buf[k & 1].z), e3 = __expf(buf[k & 1].w);

        // ---- Stage L: overwrite the just-consumed slot with position k+2 ----
        if (k + 2 < n) buf[k & 1] = __ldcs(xb + (size_t)(p0 + k + 2) * 256);

        unsigned long long ea, eb;
        PACK2(ea, e0, e1); PACK2(eb, e2, e3);

        // ---- warp partial of position k ----
        float s = (e0 + e1) + (e2 + e3);
#pragma unroll
        for (int m = 16; m > 0; m >>= 1)
            s += __shfl_xor_sync(0xffffffffu, s, m);
        if (lane == 0) red[k & 1][wid] = s;

        // ---- Stage F: accumulate position k-1 (denoms published last barrier) ----
        if (k >= 1) {
            const float4* rp = (const float4*)red[(k - 1) & 1];
            float4 ra = rp[0], rb = rp[1];
            float den = ((ra.x + ra.y) + (ra.z + ra.w))
                      + ((rb.x + rb.y) + (rb.z + rb.w));
            float inv = __fdividef(1.0f, den);
            float w1  = inv * wx;
            float w2  = inv * wy;
            float wr  = fmaf(wx, wx, wy * wy) * inv;
            unsigned long long inv2, w12, w22, wr2;
            PACK2(inv2, inv, inv); PACK2(w12, w1, w1);
            PACK2(w22, w2, w2);    PACK2(wr2, wr, wr);
            FMA2(S[0],  inv2, pe0, S[0]);  FMA2(S[1],  inv2, pe1, S[1]);
            FMA2(Sx[0], w12,  pe0, Sx[0]); FMA2(Sx[1], w12,  pe1, Sx[1]);
            FMA2(Sy[0], w22,  pe0, Sy[0]); FMA2(Sy[1], w22,  pe1, Sy[1]);
            FMA2(Sr[0], wr2,  pe0, Sr[0]); FMA2(Sr[1], wr2,  pe1, Sr[1]);
            wy += 1.0f;
            if (wy > 13.0f) { wy = 1.0f; wx += 1.0f; }
        }

        __syncthreads();

        pe0 = ea; pe1 = eb;
    }

    // ---- epilogue: accumulate final position n-1 ----
    {
        const float4* rp = (const float4*)red[(n - 1) & 1];
        float4 ra = rp[0], rb = rp[1];
        float den = ((ra.x + ra.y) + (ra.z + ra.w))
                  + ((rb.x + rb.y) + (rb.z + rb.w));
        float inv = __fdividef(1.0f, den);
        float w1  = inv * wx;
        float w2  = inv * wy;
        float wr  = fmaf(wx, wx, wy * wy) * inv;
        unsigned long long inv2, w12, w22, wr2;
        PACK2(inv2, inv, inv); PACK2(w12, w1, w1);
        PACK2(w22, w2, w2);    PACK2(wr2, wr, wr);
        FMA2(S[0],  inv2, pe0, S[0]);  FMA2(S[1],  inv2, pe1, S[1]);
        FMA2(Sx[0], w12,  pe0, Sx[0]); FMA2(Sx[1], w12,  pe1, Sx[1]);
        FMA2(Sy[0], w22,  pe0, Sy[0]); FMA2(Sy[1], w22,  pe1, Sy[1]);
        FMA2(Sr[0], wr2,  pe0, Sr[0]); FMA2(Sr[1], wr2,  pe1, Sr[1]);
    }

    // ---- coalesced partial stores: [B][SPLIT][4][CN] ----
    float* gp = g_part + (size_t)(b * SPLIT + sp) * 4 * CN;
    const int c4 = tid << 2;
    *(ulonglong2*)(gp + 0 * CN + c4) = make_ulonglong2(S[0],  S[1]);
    *(ulonglong2*)(gp + 1 * CN + c4) = make_ulonglong2(Sx[0], Sx[1]);
    *(ulonglong2*)(gp + 2 * CN + c4) = make_ulonglong2(Sy[0], Sy[1]);
    *(ulonglong2*)(gp + 3 * CN + c4) = make_ulonglong2(Sr[0], Sr[1]);
}

// ---------------------------------------------------------------------------
// Kernel 2: sum splits, per-(b,c) det, block reduce, atomicAdd scalar.
// 256 blocks x 256 thr; 8 independent float4 loads/thread (L2-resident).
// ---------------------------------------------------------------------------
__global__ __launch_bounds__(256) void final_kernel(float* __restrict__ out) {
    const int b   = blockIdx.x;
    const int tid = threadIdx.x;
    const int c4  = tid << 2;

    const float* g0 = g_part + (size_t)(b * SPLIT + 0) * 4 * CN;
    const float* g1 = g_part + (size_t)(b * SPLIT + 1) * 4 * CN;
    float4 a0 = *(const float4*)(g0 + 0 * CN + c4);
    float4 a1 = *(const float4*)(g0 + 1 * CN + c4);
    float4 a2 = *(const float4*)(g0 + 2 * CN + c4);
    float4 a3 = *(const float4*)(g0 + 3 * CN + c4);
    float4 b0 = *(const float4*)(g1 + 0 * CN + c4);
    float4 b1 = *(const float4*)(g1 + 1 * CN + c4);
    float4 b2 = *(const float4*)(g1 + 2 * CN + c4);
    float4 b3 = *(const float4*)(g1 + 3 * CN + c4);

    float m0[4] = {a0.x + b0.x, a0.y + b0.y, a0.z + b0.z, a0.w + b0.w};
    float m1[4] = {a1.x + b1.x, a1.y + b1.y, a1.z + b1.z, a1.w + b1.w};
    float m2[4] = {a2.x + b2.x, a2.y + b2.y, a2.z + b2.z, a2.w + b2.w};
    float m3[4] = {a3.x + b3.x, a3.y + b3.y, a3.z + b3.z, a3.w + b3.w};

    float acc = 0.0f;
#pragma unroll
    for (int j = 0; j < 4; ++j) {
        float s     = m0[j] + EPS_CONST;
        float inv_s = 1.0f / s;
        float mx    = m1[j] * inv_s;
        float my    = m2[j] * inv_s;
        float num   = m3[j] - 2.0f * (mx * m1[j] + my * m2[j])
                    + (mx * mx + my * my) * m0[j];
        float d     = num * inv_s * (1.0f / 169.0f);
        acc = fmaf(d * d, Z_CONST, acc);
    }

#pragma unroll
    for (int msk = 16; msk > 0; msk >>= 1)
        acc += __shfl_xor_sync(0xffffffffu, acc, msk);

    __shared__ float wsum[8];
    if ((tid & 31) == 0) wsum[tid >> 5] = acc;
    __syncthreads();
    if (tid == 0) {
        float t = ((wsum[0] + wsum[1]) + (wsum[2] + wsum[3]))
                + ((wsum[4] + wsum[5]) + (wsum[6] + wsum[7]));
        atomicAdd(out, t * (1.0f / (float)(BN * CN)));
    }
}

// ---------------------------------------------------------------------------
extern "C" void kernel_launch(void* const* d_in, const int* in_sizes, int n_in,
                              void* d_out, int out_size) {
    const float* x = (const float*)d_in[0];
    float* out = (float*)d_out;

    accum_kernel<<<BN * SPLIT, 256>>>(x, out);
    final_kernel<<<BN, 256>>>(out);
}